// round 1
// baseline (speedup 1.0000x reference)
#include <cuda_runtime.h>
#include <cstdint>

#define N_TOK 8192
#define D_IN  1024
#define F_OUT 1024
#define RANK  16

// Scratch for per-token low-rank projection r[n, :] = x[n,:] . A[id[n]]
__device__ float g_lowrank[N_TOK * RANK];

// ---------------------------------------------------------------------------
// Kernel 1: low-rank projection. One warp per token.
// r[n,j] = sum_d x[n,d] * A[id[n], d, j]    (A row-major (S, D, R), R=16)
// ---------------------------------------------------------------------------
__global__ void lowrank_kernel(const float* __restrict__ x,
                               const int*   __restrict__ ids,
                               const float* __restrict__ lora_a) {
    int warp = (blockIdx.x * blockDim.x + threadIdx.x) >> 5;
    int lane = threadIdx.x & 31;
    if (warp >= N_TOK) return;

    const float*  xr = x + (size_t)warp * D_IN;
    const float4* A  = (const float4*)(lora_a + (size_t)ids[warp] * D_IN * RANK);

    float acc[RANK];
#pragma unroll
    for (int j = 0; j < RANK; j++) acc[j] = 0.f;

    for (int d = lane; d < D_IN; d += 32) {
        float  xv = __ldg(xr + d);
        float4 a0 = A[d * 4 + 0];
        float4 a1 = A[d * 4 + 1];
        float4 a2 = A[d * 4 + 2];
        float4 a3 = A[d * 4 + 3];
        acc[0]  += xv * a0.x;  acc[1]  += xv * a0.y;
        acc[2]  += xv * a0.z;  acc[3]  += xv * a0.w;
        acc[4]  += xv * a1.x;  acc[5]  += xv * a1.y;
        acc[6]  += xv * a1.z;  acc[7]  += xv * a1.w;
        acc[8]  += xv * a2.x;  acc[9]  += xv * a2.y;
        acc[10] += xv * a2.z;  acc[11] += xv * a2.w;
        acc[12] += xv * a3.x;  acc[13] += xv * a3.y;
        acc[14] += xv * a3.z;  acc[15] += xv * a3.w;
    }

#pragma unroll
    for (int j = 0; j < RANK; j++) {
#pragma unroll
        for (int off = 16; off; off >>= 1)
            acc[j] += __shfl_xor_sync(0xffffffffu, acc[j], off);
    }
    if (lane < RANK) g_lowrank[warp * RANK + lane] = acc[lane];
}

// ---------------------------------------------------------------------------
// Kernel 2: 128x128x8 SMEM-tiled fp32 GEMM  out = x @ W, with fused epilogue
//   out[n,f] += bias[f] + sum_j r[n,j] * B[id[n], j, f]
// 256 threads, each computes an 8x8 micro-tile.
// ---------------------------------------------------------------------------
#define BM 128
#define BN 128
#define BK 8
#define TM 8
#define TN 8

__global__ __launch_bounds__(256, 2)
void gemm_lora_kernel(const float* __restrict__ x,
                      const float* __restrict__ W,
                      const float* __restrict__ bias,
                      const int*   __restrict__ ids,
                      const float* __restrict__ lora_b,
                      float*       __restrict__ out) {
    __shared__ float As[BK][BM];   // x^T tile
    __shared__ float Bs[BK][BN];   // W tile

    const int t    = threadIdx.x;
    const int tx   = t & 15;       // 0..15  -> column group
    const int ty   = t >> 4;       // 0..15  -> row group
    const int row0 = blockIdx.y * BM;
    const int col0 = blockIdx.x * BN;

    // Global-load assignments
    const int a_r = t >> 1;          // row within A tile (0..127)
    const int a_c = (t & 1) * 4;     // k offset (float4)
    const int b_k = t >> 5;          // k row within B tile (0..7)
    const int b_n = (t & 31) * 4;    // col offset (float4)

    float acc[TM][TN];
#pragma unroll
    for (int i = 0; i < TM; i++)
#pragma unroll
        for (int j = 0; j < TN; j++) acc[i][j] = 0.f;

    const float* a_ptr = x + (size_t)(row0 + a_r) * D_IN + a_c;
    const float* b_ptr = W + (size_t)b_k * F_OUT + col0 + b_n;

    for (int k0 = 0; k0 < D_IN; k0 += BK) {
        float4 av = *(const float4*)(a_ptr + k0);
        float4 bv = *(const float4*)(b_ptr + (size_t)k0 * F_OUT);

        __syncthreads();
        As[a_c + 0][a_r] = av.x;
        As[a_c + 1][a_r] = av.y;
        As[a_c + 2][a_r] = av.z;
        As[a_c + 3][a_r] = av.w;
        *(float4*)&Bs[b_k][b_n] = bv;
        __syncthreads();

#pragma unroll
        for (int k = 0; k < BK; k++) {
            float a[TM], b[TN];
#pragma unroll
            for (int i = 0; i < TM; i++) a[i] = As[k][ty * TM + i];
#pragma unroll
            for (int j = 0; j < TN; j++) b[j] = Bs[k][tx * TN + j];
#pragma unroll
            for (int i = 0; i < TM; i++)
#pragma unroll
                for (int j = 0; j < TN; j++)
                    acc[i][j] += a[i] * b[j];
        }
    }

    // Epilogue: bias + LoRA delta, then store.
    const int col = col0 + tx * TN;
    float bvec[TN];
#pragma unroll
    for (int j = 0; j < TN; j++) bvec[j] = bias[col + j];

#pragma unroll
    for (int i = 0; i < TM; i++) {
        const int row = row0 + ty * TM + i;
        const int id  = ids[row];
        const float* r    = g_lowrank + (size_t)row * RANK;
        const float* Brow = lora_b + (size_t)id * RANK * F_OUT + col;

#pragma unroll
        for (int jj = 0; jj < RANK; jj++) {
            const float  rv = r[jj];
            const float4 p0 = *(const float4*)(Brow + (size_t)jj * F_OUT);
            const float4 p1 = *(const float4*)(Brow + (size_t)jj * F_OUT + 4);
            acc[i][0] += rv * p0.x;  acc[i][1] += rv * p0.y;
            acc[i][2] += rv * p0.z;  acc[i][3] += rv * p0.w;
            acc[i][4] += rv * p1.x;  acc[i][5] += rv * p1.y;
            acc[i][6] += rv * p1.z;  acc[i][7] += rv * p1.w;
        }

        float4 o0, o1;
        o0.x = acc[i][0] + bvec[0];  o0.y = acc[i][1] + bvec[1];
        o0.z = acc[i][2] + bvec[2];  o0.w = acc[i][3] + bvec[3];
        o1.x = acc[i][4] + bvec[4];  o1.y = acc[i][5] + bvec[5];
        o1.z = acc[i][6] + bvec[6];  o1.w = acc[i][7] + bvec[7];
        *(float4*)(out + (size_t)row * F_OUT + col)     = o0;
        *(float4*)(out + (size_t)row * F_OUT + col + 4) = o1;
    }
}

// ---------------------------------------------------------------------------
// Launch
// Inputs (metadata order): x, adapter_ids, kernel(W), bias, lora_a, lora_b
// ---------------------------------------------------------------------------
extern "C" void kernel_launch(void* const* d_in, const int* in_sizes, int n_in,
                              void* d_out, int out_size) {
    const float* x      = (const float*)d_in[0];
    const int*   ids    = (const int*)  d_in[1];
    const float* W      = (const float*)d_in[2];
    const float* bias   = (const float*)d_in[3];
    const float* lora_a = (const float*)d_in[4];
    const float* lora_b = (const float*)d_in[5];
    float*       out    = (float*)d_out;

    // Kernel 1: one warp per token
    {
        int threads = 256;
        int warps_per_block = threads / 32;
        int blocks = (N_TOK + warps_per_block - 1) / warps_per_block;
        lowrank_kernel<<<blocks, threads>>>(x, ids, lora_a);
    }

    // Kernel 2: tiled GEMM + fused LoRA epilogue
    {
        dim3 grid(F_OUT / BN, N_TOK / BM);   // (8, 64)
        gemm_lora_kernel<<<grid, 256>>>(x, W, bias, ids, lora_b, out);
    }
}

// round 3
// speedup vs baseline: 1.4749x; 1.4749x over previous
#include <cuda_runtime.h>
#include <cuda_bf16.h>
#include <cstdint>

#define N_TOK 8192
#define D_IN  1024
#define F_OUT 1024
#define RANK  16

// ---------------------------------------------------------------------------
// Device scratch
// ---------------------------------------------------------------------------
__device__ __align__(16) __nv_bfloat16 g_xhi[N_TOK * D_IN];
__device__ __align__(16) __nv_bfloat16 g_xlo[N_TOK * D_IN];
__device__ __align__(16) __nv_bfloat16 g_whi[D_IN * F_OUT];
__device__ __align__(16) __nv_bfloat16 g_wlo[D_IN * F_OUT];
__device__ float g_lowrank[N_TOK * RANK];

// ---------------------------------------------------------------------------
// PTX helpers (sm_80-compatible only: cp.async, ldmatrix, mma.sync)
// ---------------------------------------------------------------------------
__device__ __forceinline__ uint32_t smem_u32(const void* p) {
    uint32_t a;
    asm("{ .reg .u64 t; cvta.to.shared.u64 t, %1; cvt.u32.u64 %0, t; }"
        : "=r"(a) : "l"(p));
    return a;
}
__device__ __forceinline__ void cp16(uint32_t dst, const void* src) {
    asm volatile("cp.async.cg.shared.global [%0], [%1], 16;" :: "r"(dst), "l"(src));
}
__device__ __forceinline__ void cp_commit() {
    asm volatile("cp.async.commit_group;" ::: "memory");
}
template <int N>
__device__ __forceinline__ void cp_wait() {
    asm volatile("cp.async.wait_group %0;" :: "n"(N) : "memory");
}
__device__ __forceinline__ void ldmx4(uint32_t* r, uint32_t addr) {
    asm volatile("ldmatrix.sync.aligned.m8n8.x4.shared.b16 {%0,%1,%2,%3}, [%4];"
                 : "=r"(r[0]), "=r"(r[1]), "=r"(r[2]), "=r"(r[3]) : "r"(addr));
}
__device__ __forceinline__ void ldmx4t(uint32_t* r, uint32_t addr) {
    asm volatile("ldmatrix.sync.aligned.m8n8.x4.trans.shared.b16 {%0,%1,%2,%3}, [%4];"
                 : "=r"(r[0]), "=r"(r[1]), "=r"(r[2]), "=r"(r[3]) : "r"(addr));
}
__device__ __forceinline__ void mma16816(float* c, const uint32_t* a, const uint32_t* b) {
    asm volatile(
        "mma.sync.aligned.m16n8k16.row.col.f32.bf16.bf16.f32 "
        "{%0,%1,%2,%3}, {%4,%5,%6,%7}, {%8,%9}, {%0,%1,%2,%3};"
        : "+f"(c[0]), "+f"(c[1]), "+f"(c[2]), "+f"(c[3])
        : "r"(a[0]), "r"(a[1]), "r"(a[2]), "r"(a[3]), "r"(b[0]), "r"(b[1]));
}

// ---------------------------------------------------------------------------
// Preprocessing: elementwise bf16 hi/lo splits
// ---------------------------------------------------------------------------
__global__ void split_kernel(const float* __restrict__ src,
                             __nv_bfloat16* __restrict__ hi,
                             __nv_bfloat16* __restrict__ lo, int n4) {
    int i = blockIdx.x * blockDim.x + threadIdx.x;
    if (i >= n4) return;
    float4 v = ((const float4*)src)[i];
    __nv_bfloat16 h[4], l[4];
    float f[4] = {v.x, v.y, v.z, v.w};
#pragma unroll
    for (int j = 0; j < 4; j++) {
        h[j] = __float2bfloat16_rn(f[j]);
        l[j] = __float2bfloat16_rn(f[j] - __bfloat162float(h[j]));
    }
    ((uint2*)hi)[i] = *(uint2*)h;
    ((uint2*)lo)[i] = *(uint2*)l;
}

// ---------------------------------------------------------------------------
// Low-rank projection: one warp per token
// ---------------------------------------------------------------------------
__global__ void lowrank_kernel(const float* __restrict__ x,
                               const int*   __restrict__ ids,
                               const float* __restrict__ lora_a) {
    int warp = (blockIdx.x * blockDim.x + threadIdx.x) >> 5;
    int lane = threadIdx.x & 31;
    if (warp >= N_TOK) return;

    const float*  xr = x + (size_t)warp * D_IN;
    const float4* A  = (const float4*)(lora_a + (size_t)ids[warp] * D_IN * RANK);

    float acc[RANK];
#pragma unroll
    for (int j = 0; j < RANK; j++) acc[j] = 0.f;

    for (int d = lane; d < D_IN; d += 32) {
        float  xv = __ldg(xr + d);
        float4 a0 = A[d * 4 + 0];
        float4 a1 = A[d * 4 + 1];
        float4 a2 = A[d * 4 + 2];
        float4 a3 = A[d * 4 + 3];
        acc[0]  += xv * a0.x;  acc[1]  += xv * a0.y;
        acc[2]  += xv * a0.z;  acc[3]  += xv * a0.w;
        acc[4]  += xv * a1.x;  acc[5]  += xv * a1.y;
        acc[6]  += xv * a1.z;  acc[7]  += xv * a1.w;
        acc[8]  += xv * a2.x;  acc[9]  += xv * a2.y;
        acc[10] += xv * a2.z;  acc[11] += xv * a2.w;
        acc[12] += xv * a3.x;  acc[13] += xv * a3.y;
        acc[14] += xv * a3.z;  acc[15] += xv * a3.w;
    }
#pragma unroll
    for (int j = 0; j < RANK; j++) {
#pragma unroll
        for (int off = 16; off; off >>= 1)
            acc[j] += __shfl_xor_sync(0xffffffffu, acc[j], off);
    }
    if (lane < RANK) g_lowrank[warp * RANK + lane] = acc[lane];
}

// ---------------------------------------------------------------------------
// Main tensor-core GEMM (mma.sync bf16, 3-term split) + fused LoRA epilogue
// CTA tile 128x128, BK=32, 8 warps (4M x 2N), double-buffered cp.async.
// ---------------------------------------------------------------------------
#define BM 128
#define BN 128
#define BK 32
#define A_STRIDE_B 80        // bytes per A smem row (32 bf16 + 8 pad)
#define B_STRIDE_B 272       // bytes per B smem row (128 bf16 + 8 pad)
#define A_BYTES (BM * A_STRIDE_B)            // 10240
#define B_BYTES (BK * B_STRIDE_B)            // 8704
#define BUF_BYTES (2 * A_BYTES + 2 * B_BYTES) // 37888
#define SMEM_TOTAL (2 * BUF_BYTES)            // 75776

__device__ __forceinline__ void load_chunk(uint32_t sb, int buf, int k0,
                                           int row0, int col0, int t) {
    uint32_t base = sb + buf * BUF_BYTES;
#pragma unroll
    for (int j = 0; j < 2; j++) {
        // A tiles: 128 rows x 64B -> 512 cp16
        int idx = t * 2 + j;
        int r = idx >> 2, q = idx & 3;
        uint32_t dst = base + r * A_STRIDE_B + q * 16;
        const __nv_bfloat16* sh = g_xhi + (size_t)(row0 + r) * D_IN + k0 + q * 8;
        const __nv_bfloat16* sl = g_xlo + (size_t)(row0 + r) * D_IN + k0 + q * 8;
        cp16(dst, sh);
        cp16(dst + A_BYTES, sl);
        // B tiles: 32 rows x 256B -> 512 cp16
        int br = idx >> 4, bs = idx & 15;
        uint32_t bdst = base + 2 * A_BYTES + br * B_STRIDE_B + bs * 16;
        const __nv_bfloat16* bh = g_whi + (size_t)(k0 + br) * F_OUT + col0 + bs * 8;
        const __nv_bfloat16* bl = g_wlo + (size_t)(k0 + br) * F_OUT + col0 + bs * 8;
        cp16(bdst, bh);
        cp16(bdst + B_BYTES, bl);
    }
}

__global__ __launch_bounds__(256)
void gemm_mma_kernel(const int*   __restrict__ ids,
                     const float* __restrict__ bias,
                     const float* __restrict__ lora_b,
                     float*       __restrict__ out) {
    extern __shared__ char smem[];
    uint32_t sb = smem_u32(smem);

    const int t      = threadIdx.x;
    const int lane   = t & 31;
    const int wid    = t >> 5;
    const int warp_m = wid & 3;        // 0..3 -> 32-row slab
    const int warp_n = wid >> 2;       // 0..1 -> 64-col slab
    const int row0   = blockIdx.y * BM;
    const int col0   = blockIdx.x * BN;

    float acc[2][8][4];
#pragma unroll
    for (int mi = 0; mi < 2; mi++)
#pragma unroll
        for (int ni = 0; ni < 8; ni++)
#pragma unroll
            for (int q = 0; q < 4; q++) acc[mi][ni][q] = 0.f;

    load_chunk(sb, 0, 0, row0, col0, t);
    cp_commit();

    const int NCH = D_IN / BK;   // 32
    for (int i = 0; i < NCH; i++) {
        int buf = i & 1;
        if (i + 1 < NCH) {
            load_chunk(sb, buf ^ 1, (i + 1) * BK, row0, col0, t);
            cp_commit();
            cp_wait<1>();
        } else {
            cp_wait<0>();
        }
        __syncthreads();

        uint32_t sa = sb + buf * BUF_BYTES;
        uint32_t sB = sa + 2 * A_BYTES;

#pragma unroll
        for (int kk = 0; kk < 2; kk++) {            // two k16 steps
            uint32_t a_hi[2][4], a_lo[2][4];
#pragma unroll
            for (int mi = 0; mi < 2; mi++) {
                int row = warp_m * 32 + mi * 16 + (lane & 15);
                int colb = (kk * 16 + (lane >> 4) * 8) * 2;
                uint32_t addr = sa + row * A_STRIDE_B + colb;
                ldmx4(a_hi[mi], addr);
                ldmx4(a_lo[mi], addr + A_BYTES);
            }
            uint32_t b_hi[4][4], b_lo[4][4];
#pragma unroll
            for (int nb = 0; nb < 4; nb++) {
                int row = kk * 16 + (lane & 15);
                int colb = (warp_n * 64 + nb * 16 + (lane >> 4) * 8) * 2;
                uint32_t addr = sB + row * B_STRIDE_B + colb;
                ldmx4t(b_hi[nb], addr);
                ldmx4t(b_lo[nb], addr + B_BYTES);
            }
#pragma unroll
            for (int mi = 0; mi < 2; mi++)
#pragma unroll
                for (int nb = 0; nb < 4; nb++) {
                    mma16816(acc[mi][nb * 2 + 0], a_hi[mi], &b_hi[nb][0]);
                    mma16816(acc[mi][nb * 2 + 1], a_hi[mi], &b_hi[nb][2]);
                    mma16816(acc[mi][nb * 2 + 0], a_hi[mi], &b_lo[nb][0]);
                    mma16816(acc[mi][nb * 2 + 1], a_hi[mi], &b_lo[nb][2]);
                    mma16816(acc[mi][nb * 2 + 0], a_lo[mi], &b_hi[nb][0]);
                    mma16816(acc[mi][nb * 2 + 1], a_lo[mi], &b_hi[nb][2]);
                }
        }
        __syncthreads();
    }

    // ------------------ Epilogue: bias + LoRA delta ------------------
    // m16n8 accum mapping: c0,c1 -> row lane/4,   cols 2*(lane%4), +1
    //                      c2,c3 -> row lane/4+8, same cols
#pragma unroll
    for (int mi = 0; mi < 2; mi++) {
#pragma unroll
        for (int h = 0; h < 2; h++) {
            const int row = row0 + warp_m * 32 + mi * 16 + (lane >> 2) + h * 8;
            const int id  = __ldg(ids + row);
            float rv[RANK];
            const float4* rp = (const float4*)(g_lowrank + (size_t)row * RANK);
#pragma unroll
            for (int q = 0; q < 4; q++) {
                float4 v = rp[q];
                rv[q * 4 + 0] = v.x; rv[q * 4 + 1] = v.y;
                rv[q * 4 + 2] = v.z; rv[q * 4 + 3] = v.w;
            }
            const float* Bb = lora_b + (size_t)id * RANK * F_OUT;
#pragma unroll
            for (int nb = 0; nb < 8; nb++) {
                const int col = col0 + warp_n * 64 + nb * 8 + (lane & 3) * 2;
                float v0 = acc[mi][nb][h * 2 + 0] + __ldg(bias + col);
                float v1 = acc[mi][nb][h * 2 + 1] + __ldg(bias + col + 1);
#pragma unroll
                for (int j = 0; j < RANK; j++) {
                    float2 w = __ldg((const float2*)(Bb + (size_t)j * F_OUT + col));
                    v0 += rv[j] * w.x;
                    v1 += rv[j] * w.y;
                }
                *(float2*)(out + (size_t)row * F_OUT + col) = make_float2(v0, v1);
            }
        }
    }
}

// ---------------------------------------------------------------------------
// Launch.  Inputs: x, adapter_ids, kernel(W), bias, lora_a, lora_b
// ---------------------------------------------------------------------------
extern "C" void kernel_launch(void* const* d_in, const int* in_sizes, int n_in,
                              void* d_out, int out_size) {
    const float* x      = (const float*)d_in[0];
    const int*   ids    = (const int*)  d_in[1];
    const float* W      = (const float*)d_in[2];
    const float* bias   = (const float*)d_in[3];
    const float* lora_a = (const float*)d_in[4];
    const float* lora_b = (const float*)d_in[5];
    float*       out    = (float*)d_out;

    static __nv_bfloat16* xhi_p = nullptr;
    // Resolve device-global addresses host-side once per process (no allocs).
    static __nv_bfloat16 *d_xhi, *d_xlo, *d_whi, *d_wlo;
    static bool init = false;
    if (!init) {
        cudaGetSymbolAddress((void**)&d_xhi, g_xhi);
        cudaGetSymbolAddress((void**)&d_xlo, g_xlo);
        cudaGetSymbolAddress((void**)&d_whi, g_whi);
        cudaGetSymbolAddress((void**)&d_wlo, g_wlo);
        cudaFuncSetAttribute(gemm_mma_kernel,
                             cudaFuncAttributeMaxDynamicSharedMemorySize, SMEM_TOTAL);
        init = true;
    }
    (void)xhi_p;

    split_kernel<<<(N_TOK * D_IN / 4 + 255) / 256, 256>>>(x, d_xhi, d_xlo, N_TOK * D_IN / 4);
    split_kernel<<<(D_IN * F_OUT / 4 + 255) / 256, 256>>>(W, d_whi, d_wlo, D_IN * F_OUT / 4);
    lowrank_kernel<<<(N_TOK * 32 + 255) / 256, 256>>>(x, ids, lora_a);

    dim3 grid(F_OUT / BN, N_TOK / BM);   // (8, 64)
    gemm_mma_kernel<<<grid, 256, SMEM_TOTAL>>>(ids, bias, lora_b, out);
}

// round 5
// speedup vs baseline: 1.6970x; 1.1506x over previous
#include <cuda_runtime.h>
#include <cuda_bf16.h>
#include <cstdint>

#define N_TOK 8192
#define D_IN  1024
#define F_OUT 1024
#define RANK  16

// ---------------------------------------------------------------------------
// Device scratch
// ---------------------------------------------------------------------------
__device__ __align__(16) __nv_bfloat16 g_xhi[N_TOK * D_IN];
__device__ __align__(16) __nv_bfloat16 g_xlo[N_TOK * D_IN];
__device__ __align__(16) __nv_bfloat16 g_whi[D_IN * F_OUT];
__device__ __align__(16) __nv_bfloat16 g_wlo[D_IN * F_OUT];
__device__ float g_lowrank[N_TOK * RANK];

// ---------------------------------------------------------------------------
// PTX helpers (sm_80-portable: cp.async, ldmatrix, mma.sync)
// ---------------------------------------------------------------------------
__device__ __forceinline__ uint32_t smem_u32(const void* p) {
    uint32_t a;
    asm("{ .reg .u64 t; cvta.to.shared.u64 t, %1; cvt.u32.u64 %0, t; }"
        : "=r"(a) : "l"(p));
    return a;
}
__device__ __forceinline__ void cp16(uint32_t dst, const void* src) {
    asm volatile("cp.async.cg.shared.global [%0], [%1], 16;" :: "r"(dst), "l"(src));
}
__device__ __forceinline__ void cp_commit() {
    asm volatile("cp.async.commit_group;" ::: "memory");
}
template <int N>
__device__ __forceinline__ void cp_wait() {
    asm volatile("cp.async.wait_group %0;" :: "n"(N) : "memory");
}
__device__ __forceinline__ void ldmx4(uint32_t* r, uint32_t addr) {
    asm volatile("ldmatrix.sync.aligned.m8n8.x4.shared.b16 {%0,%1,%2,%3}, [%4];"
                 : "=r"(r[0]), "=r"(r[1]), "=r"(r[2]), "=r"(r[3]) : "r"(addr));
}
__device__ __forceinline__ void ldmx4t(uint32_t* r, uint32_t addr) {
    asm volatile("ldmatrix.sync.aligned.m8n8.x4.trans.shared.b16 {%0,%1,%2,%3}, [%4];"
                 : "=r"(r[0]), "=r"(r[1]), "=r"(r[2]), "=r"(r[3]) : "r"(addr));
}
__device__ __forceinline__ void mma16816(float* c, const uint32_t* a, const uint32_t* b) {
    asm volatile(
        "mma.sync.aligned.m16n8k16.row.col.f32.bf16.bf16.f32 "
        "{%0,%1,%2,%3}, {%4,%5,%6,%7}, {%8,%9}, {%0,%1,%2,%3};"
        : "+f"(c[0]), "+f"(c[1]), "+f"(c[2]), "+f"(c[3])
        : "r"(a[0]), "r"(a[1]), "r"(a[2]), "r"(a[3]), "r"(b[0]), "r"(b[1]));
}

// ---------------------------------------------------------------------------
// Preprocessing: elementwise bf16 hi/lo splits
// ---------------------------------------------------------------------------
__global__ void split_kernel(const float* __restrict__ src,
                             __nv_bfloat16* __restrict__ hi,
                             __nv_bfloat16* __restrict__ lo, int n4) {
    int i = blockIdx.x * blockDim.x + threadIdx.x;
    if (i >= n4) return;
    float4 v = ((const float4*)src)[i];
    __nv_bfloat16 h[4], l[4];
    float f[4] = {v.x, v.y, v.z, v.w};
#pragma unroll
    for (int j = 0; j < 4; j++) {
        h[j] = __float2bfloat16_rn(f[j]);
        l[j] = __float2bfloat16_rn(f[j] - __bfloat162float(h[j]));
    }
    ((uint2*)hi)[i] = *(uint2*)h;
    ((uint2*)lo)[i] = *(uint2*)l;
}

// ---------------------------------------------------------------------------
// Low-rank projection: one warp per token
// ---------------------------------------------------------------------------
__global__ void lowrank_kernel(const float* __restrict__ x,
                               const int*   __restrict__ ids,
                               const float* __restrict__ lora_a) {
    int warp = (blockIdx.x * blockDim.x + threadIdx.x) >> 5;
    int lane = threadIdx.x & 31;
    if (warp >= N_TOK) return;

    const float*  xr = x + (size_t)warp * D_IN;
    const float4* A  = (const float4*)(lora_a + (size_t)ids[warp] * D_IN * RANK);

    float acc[RANK];
#pragma unroll
    for (int j = 0; j < RANK; j++) acc[j] = 0.f;

    for (int d = lane; d < D_IN; d += 32) {
        float  xv = __ldg(xr + d);
        float4 a0 = A[d * 4 + 0];
        float4 a1 = A[d * 4 + 1];
        float4 a2 = A[d * 4 + 2];
        float4 a3 = A[d * 4 + 3];
        acc[0]  += xv * a0.x;  acc[1]  += xv * a0.y;
        acc[2]  += xv * a0.z;  acc[3]  += xv * a0.w;
        acc[4]  += xv * a1.x;  acc[5]  += xv * a1.y;
        acc[6]  += xv * a1.z;  acc[7]  += xv * a1.w;
        acc[8]  += xv * a2.x;  acc[9]  += xv * a2.y;
        acc[10] += xv * a2.z;  acc[11] += xv * a2.w;
        acc[12] += xv * a3.x;  acc[13] += xv * a3.y;
        acc[14] += xv * a3.z;  acc[15] += xv * a3.w;
    }
#pragma unroll
    for (int j = 0; j < RANK; j++) {
#pragma unroll
        for (int off = 16; off; off >>= 1)
            acc[j] += __shfl_xor_sync(0xffffffffu, acc[j], off);
    }
    if (lane < RANK) g_lowrank[warp * RANK + lane] = acc[lane];
}

// ---------------------------------------------------------------------------
// Main tensor-core GEMM (mma.sync bf16, 3-term split) + fused LoRA epilogue
// CTA tile 128x128, BK=32, 8 warps (4M x 2N), double-buffered cp.async,
// 2 CTAs per SM for latency hiding.
// ---------------------------------------------------------------------------
#define BM 128
#define BN 128
#define BK 32
#define A_STRIDE_B 80        // bytes per A smem row (32 bf16 + 8 pad)
#define B_STRIDE_B 272       // bytes per B smem row (128 bf16 + 8 pad)
#define A_BYTES (BM * A_STRIDE_B)             // 10240
#define B_BYTES (BK * B_STRIDE_B)             // 8704
#define BUF_BYTES (2 * A_BYTES + 2 * B_BYTES) // 37888
#define SMEM_TOTAL (2 * BUF_BYTES)            // 75776

__device__ __forceinline__ void load_chunk(uint32_t sb, int buf, int k0,
                                           int row0, int col0, int t) {
    uint32_t base = sb + buf * BUF_BYTES;
#pragma unroll
    for (int j = 0; j < 2; j++) {
        int idx = t * 2 + j;
        // A tiles: 128 rows x 64B
        int r = idx >> 2, q = idx & 3;
        uint32_t dst = base + r * A_STRIDE_B + q * 16;
        const __nv_bfloat16* sh = g_xhi + (size_t)(row0 + r) * D_IN + k0 + q * 8;
        const __nv_bfloat16* sl = g_xlo + (size_t)(row0 + r) * D_IN + k0 + q * 8;
        cp16(dst, sh);
        cp16(dst + A_BYTES, sl);
        // B tiles: 32 rows x 256B
        int br = idx >> 4, bs = idx & 15;
        uint32_t bdst = base + 2 * A_BYTES + br * B_STRIDE_B + bs * 16;
        const __nv_bfloat16* bh = g_whi + (size_t)(k0 + br) * F_OUT + col0 + bs * 8;
        const __nv_bfloat16* bl = g_wlo + (size_t)(k0 + br) * F_OUT + col0 + bs * 8;
        cp16(bdst, bh);
        cp16(bdst + B_BYTES, bl);
    }
}

__global__ __launch_bounds__(256, 2)
void gemm_mma_kernel(const int*   __restrict__ ids,
                     const float* __restrict__ bias,
                     const float* __restrict__ lora_b,
                     float*       __restrict__ out) {
    extern __shared__ char smem[];
    uint32_t sb = smem_u32(smem);

    const int t      = threadIdx.x;
    const int lane   = t & 31;
    const int wid    = t >> 5;
    const int warp_m = wid & 3;        // 0..3 -> 32-row slab
    const int warp_n = wid >> 2;       // 0..1 -> 64-col slab
    const int row0   = blockIdx.y * BM;
    const int col0   = blockIdx.x * BN;

    float acc[2][8][4];
#pragma unroll
    for (int mi = 0; mi < 2; mi++)
#pragma unroll
        for (int ni = 0; ni < 8; ni++)
#pragma unroll
            for (int q = 0; q < 4; q++) acc[mi][ni][q] = 0.f;

    load_chunk(sb, 0, 0, row0, col0, t);
    cp_commit();

    const int NCH = D_IN / BK;   // 32
    for (int i = 0; i < NCH; i++) {
        int buf = i & 1;
        if (i + 1 < NCH) {
            load_chunk(sb, buf ^ 1, (i + 1) * BK, row0, col0, t);
            cp_commit();
            cp_wait<1>();
        } else {
            cp_wait<0>();
        }
        __syncthreads();

        uint32_t sa = sb + buf * BUF_BYTES;
        uint32_t sB = sa + 2 * A_BYTES;

#pragma unroll
        for (int kk = 0; kk < 2; kk++) {            // two k16 steps
            // A fragments for both 16-row halves (hi + lo): 16 regs
            uint32_t a_hi[2][4], a_lo[2][4];
#pragma unroll
            for (int mi = 0; mi < 2; mi++) {
                int row = warp_m * 32 + mi * 16 + (lane & 15);
                int colb = (kk * 16 + (lane >> 4) * 8) * 2;
                uint32_t addr = sa + row * A_STRIDE_B + colb;
                ldmx4(a_hi[mi], addr);
                ldmx4(a_lo[mi], addr + A_BYTES);
            }
            // B fragments loaded per 16-col block to keep register pressure low
#pragma unroll
            for (int nb = 0; nb < 4; nb++) {
                uint32_t b_hi[4], b_lo[4];
                int row = kk * 16 + (lane & 15);
                int colb = (warp_n * 64 + nb * 16 + (lane >> 4) * 8) * 2;
                uint32_t addr = sB + row * B_STRIDE_B + colb;
                ldmx4t(b_hi, addr);
                ldmx4t(b_lo, addr + B_BYTES);
                // interleave the 4 accumulators (2 mi x 2 n8) term-by-term so
                // dependent HMMAs on the same accumulator are spaced apart
#pragma unroll
                for (int mi = 0; mi < 2; mi++) {
                    mma16816(acc[mi][nb * 2 + 0], a_hi[mi], &b_hi[0]);
                    mma16816(acc[mi][nb * 2 + 1], a_hi[mi], &b_hi[2]);
                }
#pragma unroll
                for (int mi = 0; mi < 2; mi++) {
                    mma16816(acc[mi][nb * 2 + 0], a_hi[mi], &b_lo[0]);
                    mma16816(acc[mi][nb * 2 + 1], a_hi[mi], &b_lo[2]);
                }
#pragma unroll
                for (int mi = 0; mi < 2; mi++) {
                    mma16816(acc[mi][nb * 2 + 0], a_lo[mi], &b_hi[0]);
                    mma16816(acc[mi][nb * 2 + 1], a_lo[mi], &b_hi[2]);
                }
            }
        }
        __syncthreads();
    }

    // ------------------ Epilogue: bias + LoRA delta ------------------
#pragma unroll
    for (int mi = 0; mi < 2; mi++) {
#pragma unroll
        for (int h = 0; h < 2; h++) {
            const int row = row0 + warp_m * 32 + mi * 16 + (lane >> 2) + h * 8;
            const int id  = __ldg(ids + row);
            float rv[RANK];
            const float4* rp = (const float4*)(g_lowrank + (size_t)row * RANK);
#pragma unroll
            for (int q = 0; q < 4; q++) {
                float4 v = rp[q];
                rv[q * 4 + 0] = v.x; rv[q * 4 + 1] = v.y;
                rv[q * 4 + 2] = v.z; rv[q * 4 + 3] = v.w;
            }
            const float* Bb = lora_b + (size_t)id * RANK * F_OUT;
#pragma unroll
            for (int nb = 0; nb < 8; nb++) {
                const int col = col0 + warp_n * 64 + nb * 8 + (lane & 3) * 2;
                float v0 = acc[mi][nb][h * 2 + 0] + __ldg(bias + col);
                float v1 = acc[mi][nb][h * 2 + 1] + __ldg(bias + col + 1);
#pragma unroll
                for (int j = 0; j < RANK; j++) {
                    float2 w = __ldg((const float2*)(Bb + (size_t)j * F_OUT + col));
                    v0 += rv[j] * w.x;
                    v1 += rv[j] * w.y;
                }
                *(float2*)(out + (size_t)row * F_OUT + col) = make_float2(v0, v1);
            }
        }
    }
}

// ---------------------------------------------------------------------------
// Launch.  Inputs: x, adapter_ids, kernel(W), bias, lora_a, lora_b
// ---------------------------------------------------------------------------
extern "C" void kernel_launch(void* const* d_in, const int* in_sizes, int n_in,
                              void* d_out, int out_size) {
    const float* x      = (const float*)d_in[0];
    const int*   ids    = (const int*)  d_in[1];
    const float* W      = (const float*)d_in[2];
    const float* bias   = (const float*)d_in[3];
    const float* lora_a = (const float*)d_in[4];
    const float* lora_b = (const float*)d_in[5];
    float*       out    = (float*)d_out;

    static __nv_bfloat16 *d_xhi, *d_xlo, *d_whi, *d_wlo;
    static bool init = false;
    if (!init) {
        cudaGetSymbolAddress((void**)&d_xhi, g_xhi);
        cudaGetSymbolAddress((void**)&d_xlo, g_xlo);
        cudaGetSymbolAddress((void**)&d_whi, g_whi);
        cudaGetSymbolAddress((void**)&d_wlo, g_wlo);
        cudaFuncSetAttribute(gemm_mma_kernel,
                             cudaFuncAttributeMaxDynamicSharedMemorySize, SMEM_TOTAL);
        init = true;
    }

    split_kernel<<<(N_TOK * D_IN / 4 + 255) / 256, 256>>>(x, d_xhi, d_xlo, N_TOK * D_IN / 4);
    split_kernel<<<(D_IN * F_OUT / 4 + 255) / 256, 256>>>(W, d_whi, d_wlo, D_IN * F_OUT / 4);
    lowrank_kernel<<<(N_TOK * 32 + 255) / 256, 256>>>(x, ids, lora_a);

    dim3 grid(F_OUT / BN, N_TOK / BM);   // (8, 64)
    gemm_mma_kernel<<<grid, 256, SMEM_TOTAL>>>(ids, bias, lora_b, out);
}